// round 14
// baseline (speedup 1.0000x reference)
#include <cuda_runtime.h>

// ---------------------------------------------------------------------------
// 2-layer LSTM, B=2048, T=2048, I=1, H=16.
// R13 = R12 (no in-loop syncwarp, paired LDG.64/STG, prescaled sigmoid rows,
// branch-free epilogue) with accumulator-seed shaving:
//   - second subchains seeded with mul.rn.f32x2 (no zero-init MOVs;
//     bit-identical to fma with +0 addend)
//   - bias folded into the FIRST fma2 of each bias-seeded chain (no copies)
//   - #pragma unroll 2 on the pair loop (quad supersteps per trip)
// Dependency structure and live-accumulator count identical to R12.
// ---------------------------------------------------------------------------

static constexpr int B = 2048;
static constexpr int T = 2048;
static constexpr int H = 16;

#define WFENCE() asm volatile("" ::: "memory")

static __device__ __forceinline__ unsigned long long fma2(unsigned long long a,
                                                          unsigned long long b,
                                                          unsigned long long c) {
    unsigned long long d;
    asm("fma.rn.f32x2 %0, %1, %2, %3;" : "=l"(d) : "l"(a), "l"(b), "l"(c));
    return d;
}
static __device__ __forceinline__ unsigned long long mul2(unsigned long long a,
                                                          unsigned long long b) {
    unsigned long long d;
    asm("mul.rn.f32x2 %0, %1, %2;" : "=l"(d) : "l"(a), "l"(b));
    return d;
}
static __device__ __forceinline__ unsigned long long pk2(float a, float b) {
    unsigned long long r;
    asm("mov.b64 %0, {%1, %2};" : "=l"(r) : "f"(a), "f"(b));
    return r;
}
static __device__ __forceinline__ void unpk2(unsigned long long v, float& a, float& b) {
    asm("mov.b64 {%0, %1}, %2;" : "=f"(a), "=f"(b) : "l"(v));
}
static __device__ __forceinline__ float tanhA(float x) {
    float r; asm("tanh.approx.f32 %0, %1;" : "=f"(r) : "f"(x)); return r;
}

__global__ __launch_bounds__(64, 7)
void lstm2_kernel(const float* __restrict__ x,
                  const float* __restrict__ h0in,
                  const float* __restrict__ c0in,
                  const float* __restrict__ Wih0,
                  const float* __restrict__ Whh0,
                  const float* __restrict__ bih0,
                  const float* __restrict__ bhh0,
                  const float* __restrict__ Wih1,
                  const float* __restrict__ Whh1,
                  const float* __restrict__ bih1,
                  const float* __restrict__ bhh1,
                  float* __restrict__ out)
{
    __shared__ __align__(16) float smh[2][2][32];

    const int tid  = threadIdx.x;
    const int wid  = tid >> 5;
    const int lane = tid & 31;
    const int j    = lane & 15;
    const int half = lane >> 4;
    const int b    = blockIdx.x * 2 + wid;

    const int gA = half * 32 + j;
    const int gB = gA + 16;

    const float scA = half ? 1.0f : 0.5f;
    const float scB = 0.5f;

    unsigned long long w0A[8], w0B[8], wiA[8], wiB[8], w1A[8], w1B[8];
    const float2* Wh0v = reinterpret_cast<const float2*>(Whh0);
    const float2* Wi1v = reinterpret_cast<const float2*>(Wih1);
    const float2* Wh1v = reinterpret_cast<const float2*>(Whh1);
#pragma unroll
    for (int p = 0; p < 8; ++p) {
        float2 a  = Wh0v[gA * 8 + p]; w0A[p] = pk2(a.x * scA, a.y * scA);
        float2 b2 = Wh0v[gB * 8 + p]; w0B[p] = pk2(b2.x * scB, b2.y * scB);
        float2 c  = Wi1v[gA * 8 + p]; wiA[p] = pk2(c.x * scA, c.y * scA);
        float2 d  = Wi1v[gB * 8 + p]; wiB[p] = pk2(d.x * scB, d.y * scB);
        float2 e  = Wh1v[gA * 8 + p]; w1A[p] = pk2(e.x * scA, e.y * scA);
        float2 f  = Wh1v[gB * 8 + p]; w1B[p] = pk2(f.x * scB, f.y * scB);
    }
    const unsigned long long bias2A0 = pk2((bih0[gA] + bhh0[gA]) * scA, 0.0f);
    const unsigned long long bias2B0 = pk2((bih0[gB] + bhh0[gB]) * scB, 0.0f);
    const unsigned long long bias2A1 = pk2((bih1[gA] + bhh1[gA]) * scA, 0.0f);
    const unsigned long long bias2B1 = pk2((bih1[gB] + bhh1[gB]) * scB, 0.0f);
    const float wxA = Wih0[gA] * scA;
    const float wxB = Wih0[gB] * scB;
    const unsigned long long ONE2 = pk2(1.0f, 1.0f);

    const float mA = half ? 1.0f : 0.5f;
    const float cA = half ? 0.0f : 0.5f;

    float c0v = c0in[b * H + j];
    float c1v = c0in[B * H + b * H + j];
    float h0v = h0in[b * H + j];
    float h1v = h0in[B * H + b * H + j];

    float* bufA = smh[wid][0];
    float* bufB = smh[wid][1];
    bufA[j + half * 16] = half ? h1v : h0v;
    __syncwarp();

    const float* xrow = x + (size_t)b * T;
    float*       outq = out + (size_t)b * T * H + lane;

    {
        const float xv0 = __ldg(xrow);
        const ulonglong2* hp = reinterpret_cast<const ulonglong2*>(bufA);
        ulonglong2 u0 = hp[0], u1 = hp[1], u2 = hp[2], u3 = hp[3];
        unsigned long long aA  = fma2(w0A[0], u0.x, bias2A0);
        unsigned long long aB  = fma2(w0B[0], u0.x, bias2B0);
        unsigned long long aA2 = mul2(w0A[4], u2.x);
        unsigned long long aB2 = mul2(w0B[4], u2.x);
        aA  = fma2(w0A[1], u0.y, aA);   aB  = fma2(w0B[1], u0.y, aB);
        aA  = fma2(w0A[2], u1.x, aA);   aB  = fma2(w0B[2], u1.x, aB);
        aA  = fma2(w0A[3], u1.y, aA);   aB  = fma2(w0B[3], u1.y, aB);
        aA2 = fma2(w0A[5], u2.y, aA2);  aB2 = fma2(w0B[5], u2.y, aB2);
        aA2 = fma2(w0A[6], u3.x, aA2);  aB2 = fma2(w0B[6], u3.x, aB2);
        aA2 = fma2(w0A[7], u3.y, aA2);  aB2 = fma2(w0B[7], u3.y, aB2);
        aA  = fma2(aA2, ONE2, aA);      aB  = fma2(aB2, ONE2, aB);
        float aL, aH, bL, bH;
        unpk2(aA, aL, aH); unpk2(aB, bL, bH);
        const float gAraw = fmaf(xv0, wxA, aL + aH);
        const float gBraw = fmaf(xv0, wxB, bL + bH);
        const float sA = fmaf(mA, tanhA(gAraw), cA);
        const float sB = fmaf(0.5f, tanhA(gBraw), 0.5f);
        const float gg = __shfl_xor_sync(0xffffffffu, sA, 16);
        const float oo = __shfl_xor_sync(0xffffffffu, sB, 16);
        const float f_eff = half ? oo : sB;
        const float o_eff = half ? sB : oo;
        c0v = fmaf(f_eff, c0v, sA * gg);
        h0v = o_eff * tanhA(c0v);
        __syncwarp();
        if (!half) bufA[j] = h0v;
        __syncwarp();
    }

    float xv = __ldg(xrow + 1);

#define SSCORE(RB, WB)                                                         \
    {                                                                          \
        const ulonglong2* hp0 = reinterpret_cast<const ulonglong2*>(RB);       \
        const ulonglong2* hp1 = reinterpret_cast<const ulonglong2*>((RB) + 16);\
        ulonglong2 u0 = hp0[0], u1 = hp0[1], u2 = hp0[2], u3 = hp0[3];         \
        ulonglong2 v0 = hp1[0], v1 = hp1[1], v2 = hp1[2], v3 = hp1[3];         \
        unsigned long long pA  = fma2(w0A[0], u0.x, bias2A0);                  \
        unsigned long long pB  = fma2(w0B[0], u0.x, bias2B0);                  \
        unsigned long long pA2 = mul2(w0A[4], u2.x);                           \
        unsigned long long pB2 = mul2(w0B[4], u2.x);                           \
        pA  = fma2(w0A[1], u0.y, pA);   pB  = fma2(w0B[1], u0.y, pB);          \
        pA  = fma2(w0A[2], u1.x, pA);   pB  = fma2(w0B[2], u1.x, pB);          \
        pA  = fma2(w0A[3], u1.y, pA);   pB  = fma2(w0B[3], u1.y, pB);          \
        pA2 = fma2(w0A[5], u2.y, pA2);  pB2 = fma2(w0B[5], u2.y, pB2);         \
        pA2 = fma2(w0A[6], u3.x, pA2);  pB2 = fma2(w0B[6], u3.x, pB2);         \
        pA2 = fma2(w0A[7], u3.y, pA2);  pB2 = fma2(w0B[7], u3.y, pB2);         \
        unsigned long long qUA = fma2(wiA[0], u0.x, bias2A1);                  \
        unsigned long long qUB = fma2(wiB[0], u0.x, bias2B1);                  \
        unsigned long long qVA = mul2(w1A[0], v0.x);                           \
        unsigned long long qVB = mul2(w1B[0], v0.x);                           \
        qUA = fma2(wiA[1], u0.y, qUA);  qUB = fma2(wiB[1], u0.y, qUB);         \
        qVA = fma2(w1A[1], v0.y, qVA);  qVB = fma2(w1B[1], v0.y, qVB);         \
        qUA = fma2(wiA[2], u1.x, qUA);  qUB = fma2(wiB[2], u1.x, qUB);         \
        qVA = fma2(w1A[2], v1.x, qVA);  qVB = fma2(w1B[2], v1.x, qVB);         \
        qUA = fma2(wiA[3], u1.y, qUA);  qUB = fma2(wiB[3], u1.y, qUB);         \
        qVA = fma2(w1A[3], v1.y, qVA);  qVB = fma2(w1B[3], v1.y, qVB);         \
        qUA = fma2(wiA[4], u2.x, qUA);  qUB = fma2(wiB[4], u2.x, qUB);         \
        qVA = fma2(w1A[4], v2.x, qVA);  qVB = fma2(w1B[4], v2.x, qVB);         \
        qUA = fma2(wiA[5], u2.y, qUA);  qUB = fma2(wiB[5], u2.y, qUB);         \
        qVA = fma2(w1A[5], v2.y, qVA);  qVB = fma2(w1B[5], v2.y, qVB);         \
        qUA = fma2(wiA[6], u3.x, qUA);  qUB = fma2(wiB[6], u3.x, qUB);         \
        qVA = fma2(w1A[6], v3.x, qVA);  qVB = fma2(w1B[6], v3.x, qVB);         \
        qUA = fma2(wiA[7], u3.y, qUA);  qUB = fma2(wiB[7], u3.y, qUB);         \
        qVA = fma2(w1A[7], v3.y, qVA);  qVB = fma2(w1B[7], v3.y, qVB);         \
        const unsigned long long paA = fma2(pA2, ONE2, pA);                    \
        const unsigned long long paB = fma2(pB2, ONE2, pB);                    \
        const unsigned long long qaA = fma2(qVA, ONE2, qUA);                   \
        const unsigned long long qaB = fma2(qVB, ONE2, qUB);                   \
        float paL, paH, pbL, pbH, qaL, qaH, qbL, qbH;                          \
        unpk2(paA, paL, paH); unpk2(paB, pbL, pbH);                            \
        unpk2(qaA, qaL, qaH); unpk2(qaB, qbL, qbH);                            \
        const float pAraw = fmaf(xv, wxA, paL + paH);                          \
        const float pBraw = fmaf(xv, wxB, pbL + pbH);                          \
        const float qAraw = qaL + qaH;                                         \
        const float qBraw = qbL + qbH;                                         \
        const float psA = fmaf(mA, tanhA(pAraw), cA);                          \
        const float qsA = fmaf(mA, tanhA(qAraw), cA);                          \
        const float psB = fmaf(0.5f, tanhA(pBraw), 0.5f);                      \
        const float qsB = fmaf(0.5f, tanhA(qBraw), 0.5f);                      \
        const float pgg = __shfl_xor_sync(0xffffffffu, psA, 16);               \
        const float qgg = __shfl_xor_sync(0xffffffffu, qsA, 16);               \
        const float poo = __shfl_xor_sync(0xffffffffu, psB, 16);               \
        const float qoo = __shfl_xor_sync(0xffffffffu, qsB, 16);               \
        const float pf = half ? poo : psB;                                     \
        const float po = half ? psB : poo;                                     \
        const float qf = half ? qoo : qsB;                                     \
        const float qo = half ? qsB : qoo;                                     \
        c0v = fmaf(pf, c0v, psA * pgg);                                        \
        c1v = fmaf(qf, c1v, qsA * qgg);                                        \
        h0v = po * tanhA(c0v);                                                 \
        h1v = qo * tanhA(c1v);                                                 \
        (WB)[j + half * 16] = half ? h1v : h0v;                                \
        WFENCE();                                                              \
    }

    {
        float* op = outq;
#pragma unroll 2
        for (int s = 0; s < T - 3; s += 2) {
            const float2 xn2 = *reinterpret_cast<const float2*>(xrow + s + 2);
            SSCORE(bufA, bufB)
            const float h1A = h1v;
            xv = xn2.x;
            SSCORE(bufB, bufA)
            *op = half ? h1v : h1A;       // out[b,s,j] / out[b,s+1,j]
            op += 2 * H;
            xv = xn2.y;
        }
    }

    // single superstep s = T-2 (xv = x[T-1]); half0 lanes store out[b,T-2,j]
    {
        SSCORE(bufA, bufB)
        if (!half) outq[(T - 2) * H] = h1v;
    }

    // tail: layer1 step T-1 (reads bufB); half0 lanes store out[b,T-1,j]
    {
        const ulonglong2* hp0 = reinterpret_cast<const ulonglong2*>(bufB);
        const ulonglong2* hp1 = reinterpret_cast<const ulonglong2*>(bufB + 16);
        ulonglong2 u0 = hp0[0], u1 = hp0[1], u2 = hp0[2], u3 = hp0[3];
        ulonglong2 v0 = hp1[0], v1 = hp1[1], v2 = hp1[2], v3 = hp1[3];
        unsigned long long qUA = fma2(wiA[0], u0.x, bias2A1);
        unsigned long long qUB = fma2(wiB[0], u0.x, bias2B1);
        unsigned long long qVA = mul2(w1A[0], v0.x);
        unsigned long long qVB = mul2(w1B[0], v0.x);
        qUA = fma2(wiA[1], u0.y, qUA);  qUB = fma2(wiB[1], u0.y, qUB);
        qVA = fma2(w1A[1], v0.y, qVA);  qVB = fma2(w1B[1], v0.y, qVB);
        qUA = fma2(wiA[2], u1.x, qUA);  qUB = fma2(wiB[2], u1.x, qUB);
        qVA = fma2(w1A[2], v1.x, qVA);  qVB = fma2(w1B[2], v1.x, qVB);
        qUA = fma2(wiA[3], u1.y, qUA);  qUB = fma2(wiB[3], u1.y, qUB);
        qVA = fma2(w1A[3], v1.y, qVA);  qVB = fma2(w1B[3], v1.y, qVB);
        qUA = fma2(wiA[4], u2.x, qUA);  qUB = fma2(wiB[4], u2.x, qUB);
        qVA = fma2(w1A[4], v2.x, qVA);  qVB = fma2(w1B[4], v2.x, qVB);
        qUA = fma2(wiA[5], u2.y, qUA);  qUB = fma2(wiB[5], u2.y, qUB);
        qVA = fma2(w1A[5], v2.y, qVA);  qVB = fma2(w1B[5], v2.y, qVB);
        qUA = fma2(wiA[6], u3.x, qUA);  qUB = fma2(wiB[6], u3.x, qUB);
        qVA = fma2(w1A[6], v3.x, qVA);  qVB = fma2(w1B[6], v3.x, qVB);
        qUA = fma2(wiA[7], u3.y, qUA);  qUB = fma2(wiB[7], u3.y, qUB);
        qVA = fma2(w1A[7], v3.y, qVA);  qVB = fma2(w1B[7], v3.y, qVB);
        const unsigned long long qaA = fma2(qVA, ONE2, qUA);
        const unsigned long long qaB = fma2(qVB, ONE2, qUB);
        float qaL, qaH, qbL, qbH;
        unpk2(qaA, qaL, qaH); unpk2(qaB, qbL, qbH);
        const float qAraw = qaL + qaH;
        const float qBraw = qbL + qbH;
        const float qsA = fmaf(mA, tanhA(qAraw), cA);
        const float qsB = fmaf(0.5f, tanhA(qBraw), 0.5f);
        const float qgg = __shfl_xor_sync(0xffffffffu, qsA, 16);
        const float qoo = __shfl_xor_sync(0xffffffffu, qsB, 16);
        const float qf = half ? qoo : qsB;
        const float qo = half ? qsB : qoo;
        c1v = fmaf(qf, c1v, qsA * qgg);
        h1v = qo * tanhA(c1v);
        if (!half) outq[(T - 1) * H] = h1v;
    }

    {
        float* hN = out + (size_t)B * T * H;
        float* cN = hN + 2 * B * H;
        const int off = half * (B * H) + b * H + j;
        hN[off] = half ? h1v : h0v;
        cN[off] = half ? c1v : c0v;
    }
}

extern "C" void kernel_launch(void* const* d_in, const int* in_sizes, int n_in,
                              void* d_out, int out_size) {
    const float* x    = (const float*)d_in[0];
    const float* h0   = (const float*)d_in[1];
    const float* c0   = (const float*)d_in[2];
    const float* Wih0 = (const float*)d_in[3];
    const float* Whh0 = (const float*)d_in[4];
    const float* bih0 = (const float*)d_in[5];
    const float* bhh0 = (const float*)d_in[6];
    const float* Wih1 = (const float*)d_in[7];
    const float* Whh1 = (const float*)d_in[8];
    const float* bih1 = (const float*)d_in[9];
    const float* bhh1 = (const float*)d_in[10];
    float* out = (float*)d_out;

    lstm2_kernel<<<B / 2, 64>>>(x, h0, c0, Wih0, Whh0, bih0, bhh0,
                                Wih1, Whh1, bih1, bhh1, out);
}

// round 17
// speedup vs baseline: 1.6308x; 1.6308x over previous
#include <cuda_runtime.h>

// ---------------------------------------------------------------------------
// 2-layer LSTM, B=2048, T=2048, I=1, H=16.
// R15 (resubmit after infra failure) = R12 EXACTLY (SSCORE body byte-identical:
// MOV-seeded accumulators, bias2 registers as fma2 init operands, fma2-only
// chains -- this idiom keeps FFMA2 pairing intact, proven by R12=943us vs
// R13=1540us unpairing) with ONE isolated change: #pragma unroll 2 on the
// superstep-pair loop.
// ---------------------------------------------------------------------------

static constexpr int B = 2048;
static constexpr int T = 2048;
static constexpr int H = 16;

#define WFENCE() asm volatile("" ::: "memory")

static __device__ __forceinline__ unsigned long long fma2(unsigned long long a,
                                                          unsigned long long b,
                                                          unsigned long long c) {
    unsigned long long d;
    asm("fma.rn.f32x2 %0, %1, %2, %3;" : "=l"(d) : "l"(a), "l"(b), "l"(c));
    return d;
}
static __device__ __forceinline__ unsigned long long pk2(float a, float b) {
    unsigned long long r;
    asm("mov.b64 %0, {%1, %2};" : "=l"(r) : "f"(a), "f"(b));
    return r;
}
static __device__ __forceinline__ void unpk2(unsigned long long v, float& a, float& b) {
    asm("mov.b64 {%0, %1}, %2;" : "=f"(a), "=f"(b) : "l"(v));
}
static __device__ __forceinline__ float tanhA(float x) {
    float r; asm("tanh.approx.f32 %0, %1;" : "=f"(r) : "f"(x)); return r;
}

__global__ __launch_bounds__(64, 7)
void lstm2_kernel(const float* __restrict__ x,
                  const float* __restrict__ h0in,
                  const float* __restrict__ c0in,
                  const float* __restrict__ Wih0,
                  const float* __restrict__ Whh0,
                  const float* __restrict__ bih0,
                  const float* __restrict__ bhh0,
                  const float* __restrict__ Wih1,
                  const float* __restrict__ Whh1,
                  const float* __restrict__ bih1,
                  const float* __restrict__ bhh1,
                  float* __restrict__ out)
{
    __shared__ __align__(16) float smh[2][2][32];

    const int tid  = threadIdx.x;
    const int wid  = tid >> 5;
    const int lane = tid & 31;
    const int j    = lane & 15;
    const int half = lane >> 4;
    const int b    = blockIdx.x * 2 + wid;

    const int gA = half * 32 + j;
    const int gB = gA + 16;

    const float scA = half ? 1.0f : 0.5f;
    const float scB = 0.5f;

    unsigned long long w0A[8], w0B[8], wiA[8], wiB[8], w1A[8], w1B[8];
    const float2* Wh0v = reinterpret_cast<const float2*>(Whh0);
    const float2* Wi1v = reinterpret_cast<const float2*>(Wih1);
    const float2* Wh1v = reinterpret_cast<const float2*>(Whh1);
#pragma unroll
    for (int p = 0; p < 8; ++p) {
        float2 a  = Wh0v[gA * 8 + p]; w0A[p] = pk2(a.x * scA, a.y * scA);
        float2 b2 = Wh0v[gB * 8 + p]; w0B[p] = pk2(b2.x * scB, b2.y * scB);
        float2 c  = Wi1v[gA * 8 + p]; wiA[p] = pk2(c.x * scA, c.y * scA);
        float2 d  = Wi1v[gB * 8 + p]; wiB[p] = pk2(d.x * scB, d.y * scB);
        float2 e  = Wh1v[gA * 8 + p]; w1A[p] = pk2(e.x * scA, e.y * scA);
        float2 f  = Wh1v[gB * 8 + p]; w1B[p] = pk2(f.x * scB, f.y * scB);
    }
    const unsigned long long bias2A0 = pk2((bih0[gA] + bhh0[gA]) * scA, 0.0f);
    const unsigned long long bias2B0 = pk2((bih0[gB] + bhh0[gB]) * scB, 0.0f);
    const unsigned long long bias2A1 = pk2((bih1[gA] + bhh1[gA]) * scA, 0.0f);
    const unsigned long long bias2B1 = pk2((bih1[gB] + bhh1[gB]) * scB, 0.0f);
    const float wxA = Wih0[gA] * scA;
    const float wxB = Wih0[gB] * scB;
    const unsigned long long ONE2 = pk2(1.0f, 1.0f);

    const float mA = half ? 1.0f : 0.5f;
    const float cA = half ? 0.0f : 0.5f;

    float c0v = c0in[b * H + j];
    float c1v = c0in[B * H + b * H + j];
    float h0v = h0in[b * H + j];
    float h1v = h0in[B * H + b * H + j];

    float* bufA = smh[wid][0];
    float* bufB = smh[wid][1];
    bufA[j + half * 16] = half ? h1v : h0v;
    __syncwarp();

    const float* xrow = x + (size_t)b * T;
    float*       outq = out + (size_t)b * T * H + lane;

    {
        const float xv0 = __ldg(xrow);
        const ulonglong2* hp = reinterpret_cast<const ulonglong2*>(bufA);
        ulonglong2 u0 = hp[0], u1 = hp[1], u2 = hp[2], u3 = hp[3];
        unsigned long long aA = bias2A0, aB = bias2B0, aA2 = 0ull, aB2 = 0ull;
        aA  = fma2(w0A[0], u0.x, aA);   aB  = fma2(w0B[0], u0.x, aB);
        aA  = fma2(w0A[1], u0.y, aA);   aB  = fma2(w0B[1], u0.y, aB);
        aA  = fma2(w0A[2], u1.x, aA);   aB  = fma2(w0B[2], u1.x, aB);
        aA  = fma2(w0A[3], u1.y, aA);   aB  = fma2(w0B[3], u1.y, aB);
        aA2 = fma2(w0A[4], u2.x, aA2);  aB2 = fma2(w0B[4], u2.x, aB2);
        aA2 = fma2(w0A[5], u2.y, aA2);  aB2 = fma2(w0B[5], u2.y, aB2);
        aA2 = fma2(w0A[6], u3.x, aA2);  aB2 = fma2(w0B[6], u3.x, aB2);
        aA2 = fma2(w0A[7], u3.y, aA2);  aB2 = fma2(w0B[7], u3.y, aB2);
        aA  = fma2(aA2, ONE2, aA);      aB  = fma2(aB2, ONE2, aB);
        float aL, aH, bL, bH;
        unpk2(aA, aL, aH); unpk2(aB, bL, bH);
        const float gAraw = fmaf(xv0, wxA, aL + aH);
        const float gBraw = fmaf(xv0, wxB, bL + bH);
        const float sA = fmaf(mA, tanhA(gAraw), cA);
        const float sB = fmaf(0.5f, tanhA(gBraw), 0.5f);
        const float gg = __shfl_xor_sync(0xffffffffu, sA, 16);
        const float oo = __shfl_xor_sync(0xffffffffu, sB, 16);
        const float f_eff = half ? oo : sB;
        const float o_eff = half ? sB : oo;
        c0v = fmaf(f_eff, c0v, sA * gg);
        h0v = o_eff * tanhA(c0v);
        __syncwarp();
        if (!half) bufA[j] = h0v;
        __syncwarp();
    }

    float xv = __ldg(xrow + 1);

#define SSCORE(RB, WB)                                                         \
    {                                                                          \
        const ulonglong2* hp0 = reinterpret_cast<const ulonglong2*>(RB);       \
        const ulonglong2* hp1 = reinterpret_cast<const ulonglong2*>((RB) + 16);\
        ulonglong2 u0 = hp0[0], u1 = hp0[1], u2 = hp0[2], u3 = hp0[3];         \
        ulonglong2 v0 = hp1[0], v1 = hp1[1], v2 = hp1[2], v3 = hp1[3];         \
        unsigned long long pA = bias2A0, pB = bias2B0, pA2 = 0ull, pB2 = 0ull; \
        pA  = fma2(w0A[0], u0.x, pA);   pB  = fma2(w0B[0], u0.x, pB);          \
        pA  = fma2(w0A[1], u0.y, pA);   pB  = fma2(w0B[1], u0.y, pB);          \
        pA  = fma2(w0A[2], u1.x, pA);   pB  = fma2(w0B[2], u1.x, pB);          \
        pA  = fma2(w0A[3], u1.y, pA);   pB  = fma2(w0B[3], u1.y, pB);          \
        pA2 = fma2(w0A[4], u2.x, pA2);  pB2 = fma2(w0B[4], u2.x, pB2);         \
        pA2 = fma2(w0A[5], u2.y, pA2);  pB2 = fma2(w0B[5], u2.y, pB2);         \
        pA2 = fma2(w0A[6], u3.x, pA2);  pB2 = fma2(w0B[6], u3.x, pB2);         \
        pA2 = fma2(w0A[7], u3.y, pA2);  pB2 = fma2(w0B[7], u3.y, pB2);         \
        unsigned long long qUA = bias2A1, qUB = bias2B1;                       \
        unsigned long long qVA = 0ull,   qVB = 0ull;                           \
        qUA = fma2(wiA[0], u0.x, qUA);  qUB = fma2(wiB[0], u0.x, qUB);         \
        qVA = fma2(w1A[0], v0.x, qVA);  qVB = fma2(w1B[0], v0.x, qVB);         \
        qUA = fma2(wiA[1], u0.y, qUA);  qUB = fma2(wiB[1], u0.y, qUB);         \
        qVA = fma2(w1A[1], v0.y, qVA);  qVB = fma2(w1B[1], v0.y, qVB);         \
        qUA = fma2(wiA[2], u1.x, qUA);  qUB = fma2(wiB[2], u1.x, qUB);         \
        qVA = fma2(w1A[2], v1.x, qVA);  qVB = fma2(w1B[2], v1.x, qVB);         \
        qUA = fma2(wiA[3], u1.y, qUA);  qUB = fma2(wiB[3], u1.y, qUB);         \
        qVA = fma2(w1A[3], v1.y, qVA);  qVB = fma2(w1B[3], v1.y, qVB);         \
        qUA = fma2(wiA[4], u2.x, qUA);  qUB = fma2(wiB[4], u2.x, qUB);         \
        qVA = fma2(w1A[4], v2.x, qVA);  qVB = fma2(w1B[4], v2.x, qVB);         \
        qUA = fma2(wiA[5], u2.y, qUA);  qUB = fma2(wiB[5], u2.y, qUB);         \
        qVA = fma2(w1A[5], v2.y, qVA);  qVB = fma2(w1B[5], v2.y, qVB);         \
        qUA = fma2(wiA[6], u3.x, qUA);  qUB = fma2(wiB[6], u3.x, qUB);         \
        qVA = fma2(w1A[6], v3.x, qVA);  qVB = fma2(w1B[6], v3.x, qVB);         \
        qUA = fma2(wiA[7], u3.y, qUA);  qUB = fma2(wiB[7], u3.y, qUB);         \
        qVA = fma2(w1A[7], v3.y, qVA);  qVB = fma2(w1B[7], v3.y, qVB);         \
        const unsigned long long paA = fma2(pA2, ONE2, pA);                    \
        const unsigned long long paB = fma2(pB2, ONE2, pB);                    \
        const unsigned long long qaA = fma2(qVA, ONE2, qUA);                   \
        const unsigned long long qaB = fma2(qVB, ONE2, qUB);                   \
        float paL, paH, pbL, pbH, qaL, qaH, qbL, qbH;                          \
        unpk2(paA, paL, paH); unpk2(paB, pbL, pbH);                            \
        unpk2(qaA, qaL, qaH); unpk2(qaB, qbL, qbH);                            \
        const float pAraw = fmaf(xv, wxA, paL + paH);                          \
        const float pBraw = fmaf(xv, wxB, pbL + pbH);                          \
        const float qAraw = qaL + qaH;                                         \
        const float qBraw = qbL + qbH;                                         \
        const float psA = fmaf(mA, tanhA(pAraw), cA);                          \
        const float qsA = fmaf(mA, tanhA(qAraw), cA);                          \
        const float psB = fmaf(0.5f, tanhA(pBraw), 0.5f);                      \
        const float qsB = fmaf(0.5f, tanhA(qBraw), 0.5f);                      \
        const float pgg = __shfl_xor_sync(0xffffffffu, psA, 16);               \
        const float qgg = __shfl_xor_sync(0xffffffffu, qsA, 16);               \
        const float poo = __shfl_xor_sync(0xffffffffu, psB, 16);               \
        const float qoo = __shfl_xor_sync(0xffffffffu, qsB, 16);               \
        const float pf = half ? poo : psB;                                     \
        const float po = half ? psB : poo;                                     \
        const float qf = half ? qoo : qsB;                                     \
        const float qo = half ? qsB : qoo;                                     \
        c0v = fmaf(pf, c0v, psA * pgg);                                        \
        c1v = fmaf(qf, c1v, qsA * qgg);                                        \
        h0v = po * tanhA(c0v);                                                 \
        h1v = qo * tanhA(c1v);                                                 \
        (WB)[j + half * 16] = half ? h1v : h0v;                                \
        WFENCE();                                                              \
    }

    {
        float* op = outq;
#pragma unroll 2
        for (int s = 0; s < T - 3; s += 2) {
            const float2 xn2 = *reinterpret_cast<const float2*>(xrow + s + 2);
            SSCORE(bufA, bufB)
            const float h1A = h1v;
            xv = xn2.x;
            SSCORE(bufB, bufA)
            *op = half ? h1v : h1A;       // out[b,s,j] / out[b,s+1,j]
            op += 2 * H;
            xv = xn2.y;
        }
    }

    // single superstep s = T-2 (xv = x[T-1]); half0 lanes store out[b,T-2,j]
    {
        SSCORE(bufA, bufB)
        if (!half) outq[(T - 2) * H] = h1v;
    }

    // tail: layer1 step T-1 (reads bufB); half0 lanes store out[b,T-1,j]
    {
        const ulonglong2* hp0 = reinterpret_cast<const ulonglong2*>(bufB);
        const ulonglong2* hp1 = reinterpret_cast<const ulonglong2*>(bufB + 16);
        ulonglong2 u0 = hp0[0], u1 = hp0[1], u2 = hp0[2], u3 = hp0[3];
        ulonglong2 v0 = hp1[0], v1 = hp1[1], v2 = hp1[2], v3 = hp1[3];
        unsigned long long qUA = bias2A1, qUB = bias2B1;
        unsigned long long qVA = 0ull,   qVB = 0ull;
        qUA = fma2(wiA[0], u0.x, qUA);  qUB = fma2(wiB[0], u0.x, qUB);
        qVA = fma2(w1A[0], v0.x, qVA);  qVB = fma2(w1B[0], v0.x, qVB);
        qUA = fma2(wiA[1], u0.y, qUA);  qUB = fma2(wiB[1], u0.y, qUB);
        qVA = fma2(w1A[1], v0.y, qVA);  qVB = fma2(w1B[1], v0.y, qVB);
        qUA = fma2(wiA[2], u1.x, qUA);  qUB = fma2(wiB[2], u1.x, qUB);
        qVA = fma2(w1A[2], v1.x, qVA);  qVB = fma2(w1B[2], v1.x, qVB);
        qUA = fma2(wiA[3], u1.y, qUA);  qUB = fma2(wiB[3], u1.y, qUB);
        qVA = fma2(w1A[3], v1.y, qVA);  qVB = fma2(w1B[3], v1.y, qVB);
        qUA = fma2(wiA[4], u2.x, qUA);  qUB = fma2(wiB[4], u2.x, qUB);
        qVA = fma2(w1A[4], v2.x, qVA);  qVB = fma2(w1B[4], v2.x, qVB);
        qUA = fma2(wiA[5], u2.y, qUA);  qUB = fma2(wiB[5], u2.y, qUB);
        qVA = fma2(w1A[5], v2.y, qVA);  qVB = fma2(w1B[5], v2.y, qVB);
        qUA = fma2(wiA[6], u3.x, qUA);  qUB = fma2(wiB[6], u3.x, qUB);
        qVA = fma2(w1A[6], v3.x, qVA);  qVB = fma2(w1B[6], v3.x, qVB);
        qUA = fma2(wiA[7], u3.y, qUA);  qUB = fma2(wiB[7], u3.y, qUB);
        qVA = fma2(w1A[7], v3.y, qVA);  qVB = fma2(w1B[7], v3.y, qVB);
        const unsigned long long qaA = fma2(qVA, ONE2, qUA);
        const unsigned long long qaB = fma2(qVB, ONE2, qUB);
        float qaL, qaH, qbL, qbH;
        unpk2(qaA, qaL, qaH); unpk2(qaB, qbL, qbH);
        const float qAraw = qaL + qaH;
        const float qBraw = qbL + qbH;
        const float qsA = fmaf(mA, tanhA(qAraw), cA);
        const float qsB = fmaf(0.5f, tanhA(qBraw), 0.5f);
        const float qgg = __shfl_xor_sync(0xffffffffu, qsA, 16);
        const float qoo = __shfl_xor_sync(0xffffffffu, qsB, 16);
        const float qf = half ? qoo : qsB;
        const float qo = half ? qsB : qoo;
        c1v = fmaf(qf, c1v, qsA * qgg);
        h1v = qo * tanhA(c1v);
        if (!half) outq[(T - 1) * H] = h1v;
    }

    {
        float* hN = out + (size_t)B * T * H;
        float* cN = hN + 2 * B * H;
        const int off = half * (B * H) + b * H + j;
        hN[off] = half ? h1v : h0v;
        cN[off] = half ? c1v : c0v;
    }
}

extern "C" void kernel_launch(void* const* d_in, const int* in_sizes, int n_in,
                              void* d_out, int out_size) {
    const float* x    = (const float*)d_in[0];
    const float* h0   = (const float*)d_in[1];
    const float* c0   = (const float*)d_in[2];
    const float* Wih0 = (const float*)d_in[3];
    const float* Whh0 = (const float*)d_in[4];
    const float* bih0 = (const float*)d_in[5];
    const float* bhh0 = (const float*)d_in[6];
    const float* Wih1 = (const float*)d_in[7];
    const float* Whh1 = (const float*)d_in[8];
    const float* bih1 = (const float*)d_in[9];
    const float* bhh1 = (const float*)d_in[10];
    float* out = (float*)d_out;

    lstm2_kernel<<<B / 2, 64>>>(x, h0, c0, Wih0, Whh0, bih0, bhh0,
                                Wih1, Whh1, bih1, bhh1, out);
}